// round 6
// baseline (speedup 1.0000x reference)
#include <cuda_runtime.h>
#include <cstdint>

// Problem constants
#define BB 4
#define LL 4096
#define DD 768
#define CH 128            // chunks per batch
#define CROWS 32          // rows per chunk (CH*CROWS = LL)
#define NB 296            // total blocks = 148 SMs x 2 (guaranteed co-resident)
#define RB 128            // reader blocks
#define CB 40             // ctx blocks
#define WROWS 16          // rows per write item
#define ITEMS (BB * LL / WROWS)   // 1024
#define OPB 20            // ctx outputs per block (40*20 >= 768)

// Scratch + flags (device globals)
__device__ float g_partial[CH][BB][DD];
__device__ float g_wsum[CH][BB];
__device__ float g_hbar[BB][DD];
__device__ float g_ctx[BB][DD];
__device__ int   g_done[BB];     // reader chunks finished per batch
__device__ int   g_hdone[BB];    // ctx blocks past hbar stage
__device__ int   g_cdone[BB];    // ctx blocks past gemv stage
__device__ int   g_ticket;       // writer work-stealing ticket
__device__ float g_sink;

__global__ void reset_kernel() {
    if (threadIdx.x < BB) {
        g_done[threadIdx.x] = 0; g_hdone[threadIdx.x] = 0; g_cdone[threadIdx.x] = 0;
    }
    if (threadIdx.x == 0) g_ticket = 0;
}

__device__ __forceinline__ int vload(const int* p) { return *(volatile const int*)p; }
__device__ __forceinline__ void spin_ge(const int* p, int target) {
    while (vload(p) < target) __nanosleep(64);
}

// ---------------------------------------------------------------------------
// Fused pipeline: readers (wsum) -> ctx (reduce+gemv) -> writers (bcast),
// overlapped via flags. Writes of batch b start while later batches still read.
// mask is {0,-1e9} => weights exactly {1,0}: dead rows skipped, softmax
// normalization deferred (divide by total weight in hbar stage).
// ---------------------------------------------------------------------------
__global__ void __launch_bounds__(192, 2) fused_kernel(
    const float* __restrict__ hs, const float* __restrict__ mask,
    const float* __restrict__ Wv, const float* __restrict__ bv,
    float* __restrict__ out)
{
    const int B = blockIdx.x;
    const int t = threadIdx.x;                 // 192 = DD/4
    __shared__ float  p[CROWS];
    __shared__ float  s_invw;
    __shared__ float4 s_h4[DD / 4];
    __shared__ int    s_item;

    if (B < RB) {
        // ---------------- READER: one chunk per batch, batches in order ----
        const int c = B;
        for (int b = 0; b < BB; b++) {
            if (t < CROWS) {                   // warp 0
                float w = expf(__ldg(&mask[(size_t)b * LL + c * CROWS + t]));
                p[t] = w;
                #pragma unroll
                for (int o = 16; o > 0; o >>= 1) w += __shfl_down_sync(0xffffffffu, w, o);
                if (t == 0) g_wsum[c][b] = w;
            }
            __syncthreads();

            const float4* __restrict__ src =
                (const float4*)(hs + ((size_t)b * LL + (size_t)c * CROWS) * DD);
            float4 acc = make_float4(0.f, 0.f, 0.f, 0.f);
            #pragma unroll 8
            for (int r = 0; r < CROWS; r++) {
                const float pr = p[r];
                if (pr != 0.0f) {              // uniform branch: skip dead rows
                    const float4 x = src[(size_t)r * (DD / 4) + t];
                    acc.x = fmaf(pr, x.x, acc.x);
                    acc.y = fmaf(pr, x.y, acc.y);
                    acc.z = fmaf(pr, x.z, acc.z);
                    acc.w = fmaf(pr, x.w, acc.w);
                }
            }
            ((float4*)g_partial[c][b])[t] = acc;
            __threadfence();
            __syncthreads();                   // all fences done before release
            if (t == 0) atomicAdd(&g_done[b], 1);
        }
    } else if (B < RB + CB) {
        // ---------------- CTX: Wv prefetch, then reduce+gemv per batch -----
        const int j = B - RB;
        {   // warm Wv into L2 while readers stream (otherwise idle time)
            const float4* __restrict__ w4 = (const float4*)Wv;
            float a = 0.f;
            #pragma unroll
            for (int i = 0; i < 20; i++) {
                const int idx = (j * 192 + t) + i * (CB * 192);
                if (idx < DD * DD / 4) {
                    const float4 v = __ldg(&w4[idx]);
                    a += v.x + v.y + v.z + v.w;
                }
            }
            if (a == 1.23456789e30f) g_sink = a;   // never true; defeats DCE
        }
        const int o0 = j * OPB;
        const int o1 = (o0 + OPB < DD) ? o0 + OPB : DD;
        for (int b = 0; b < BB; b++) {
            if (t == 0) spin_ge(&g_done[b], RB);
            __syncthreads();
            __threadfence();
            if (t < 32) {                      // total weight -> 1/sum
                float s = g_wsum[t][b] + g_wsum[t + 32][b] +
                          g_wsum[t + 64][b] + g_wsum[t + 96][b];
                #pragma unroll
                for (int o = 16; o > 0; o >>= 1) s += __shfl_down_sync(0xffffffffu, s, o);
                if (t == 0) s_invw = 1.0f / s;
            }
            __syncthreads();
            {   // hbar: 24 groups of 8 threads; group g -> output o0+g
                const int g = t >> 3, sub = t & 7;
                const int o = o0 + g;
                if (o < o1) {
                    float s = 0.f;
                    #pragma unroll
                    for (int k = 0; k < CH / 8; k++)
                        s += g_partial[sub * (CH / 8) + k][b][o];
                    #pragma unroll
                    for (int off = 4; off > 0; off >>= 1)
                        s += __shfl_down_sync(0xffffffffu, s, off, 8);
                    if (sub == 0) g_hbar[b][o] = s * s_invw;
                }
            }
            __threadfence();
            __syncthreads();
            if (t == 0) { atomicAdd(&g_hdone[b], 1); spin_ge(&g_hdone[b], CB); }
            __syncthreads();
            __threadfence();
            s_h4[t] = __ldg(&((const float4*)g_hbar[b])[t]);   // full hbar row
            __syncthreads();
            {   // gemv: 6 warps, outputs round-robin
                const int w = t >> 5, lane = t & 31;
                for (int o = o0 + w; o < o1; o += 6) {
                    const float4* __restrict__ wv4 = (const float4*)(Wv + (size_t)o * DD);
                    float acc = 0.f;
                    #pragma unroll
                    for (int i = 0; i < 6; i++) {
                        const float4 wv = __ldg(&wv4[lane + 32 * i]);
                        const float4 hv = s_h4[lane + 32 * i];
                        acc = fmaf(wv.x, hv.x, fmaf(wv.y, hv.y,
                              fmaf(wv.z, hv.z, fmaf(wv.w, hv.w, acc))));
                    }
                    #pragma unroll
                    for (int off = 16; off > 0; off >>= 1)
                        acc += __shfl_down_sync(0xffffffffu, acc, off);
                    if (lane == 0) g_ctx[b][o] = acc + __ldg(&bv[o]);
                }
            }
            __threadfence();
            __syncthreads();
            if (t == 0) atomicAdd(&g_cdone[b], 1);
        }
    }

    // ---------------- WRITER: all blocks join after their role work --------
    int curb = -1;
    float4 v = make_float4(0.f, 0.f, 0.f, 0.f);
    for (;;) {
        __syncthreads();
        if (t == 0) s_item = atomicAdd(&g_ticket, 1);
        __syncthreads();
        const int item = s_item;
        if (item >= ITEMS) break;
        const int b = item >> 8;               // 256 items per batch, in order
        if (b != curb) {
            if (t == 0) spin_ge(&g_cdone[b], CB);
            __syncthreads();
            __threadfence();
            v = __ldg(&((const float4*)g_ctx[b])[t]);
            curb = b;
        }
        float4* __restrict__ dst =
            (float4*)(out + ((size_t)b * LL + (size_t)(item & 255) * WROWS) * DD);
        #pragma unroll
        for (int r = 0; r < WROWS; r++)
            dst[(size_t)r * (DD / 4) + t] = v;
    }
}

// ---------------------------------------------------------------------------
// Inputs: hidden_states, attention_mask, Wq, bq, Wk, bk, Wv, bv (Q/K dead)
// ---------------------------------------------------------------------------
extern "C" void kernel_launch(void* const* d_in, const int* in_sizes, int n_in,
                              void* d_out, int out_size) {
    const float* hs   = (const float*)d_in[0];
    const float* mask = (const float*)d_in[1];
    const float* Wv   = (const float*)d_in[6];
    const float* bv   = (const float*)d_in[7];
    float* out = (float*)d_out;

    reset_kernel<<<1, 32>>>();
    fused_kernel<<<NB, 192>>>(hs, mask, Wv, bv, out);
}